// round 2
// baseline (speedup 1.0000x reference)
#include <cuda_runtime.h>
#include <cstdint>

// Problem constants
#define BB 8
#define SS 2048
#define EE 1024
#define HH 64
#define BSROWS (BB*SS)   // 16384

// ---------------- scratch (device globals; no allocation allowed) ----------
__device__ float g_Q[BB*SS*HH];
__device__ float g_K[BB*SS*HH];
__device__ float g_V[BB*SS*HH];
__device__ int   g_mask_mode;   // 0 = int32, 1 = uint8/bool, 2 = float32

// ---------------- mask dtype detection -------------------------------------
// jax bool may arrive as 1-byte bool, promoted int32, or float32. Classify by
// inspecting the first 256 32-bit words (mask buffer is >= 33 MB, safe).
__global__ void detect_mask_kernel(const unsigned int* __restrict__ m) {
    if (threadIdx.x == 0 && blockIdx.x == 0) {
        bool all_01 = true;      // int32 with values {0,1}
        bool all_f  = true;      // float32 with values {0.0f,1.0f}
        for (int i = 0; i < 256; i++) {
            unsigned v = m[i];
            if (v > 1u) all_01 = false;
            if (v != 0u && v != 0x3F800000u) all_f = false;
        }
        g_mask_mode = all_01 ? 0 : (all_f ? 2 : 1);
    }
}

// ---------------- fused QKV projection -------------------------------------
// C[M=16384, N=64] = A[M,1024] @ W[1024,64] + bias.  blockIdx.y selects Q/K/V.
// 64x64 output tile per block, K-tiles of 32, 4x4 register microtile / thread.
__global__ __launch_bounds__(256) void proj_kernel(
    const float* __restrict__ A0, const float* __restrict__ A1, const float* __restrict__ A2,
    const float* __restrict__ W0, const float* __restrict__ W1, const float* __restrict__ W2,
    const float* __restrict__ b0, const float* __restrict__ b1, const float* __restrict__ b2)
{
    const float *A, *W, *bias; float* C;
    if (blockIdx.y == 0)      { A = A0; W = W0; bias = b0; C = g_Q; }
    else if (blockIdx.y == 1) { A = A1; W = W1; bias = b1; C = g_K; }
    else                      { A = A2; W = W2; bias = b2; C = g_V; }

    __shared__ float As[32][65];   // A tile transposed: As[k][m]
    __shared__ float Ws[32][64];   // W tile:            Ws[k][n]

    const int tid = threadIdx.x;
    const int tx  = tid & 15;      // 16 col-groups (n)
    const int ty  = tid >> 4;      // 16 row-groups (m)
    const int row0 = blockIdx.x * 64;

    float acc[4][4] = {};

    for (int k0 = 0; k0 < EE; k0 += 32) {
        #pragma unroll
        for (int i = 0; i < 8; i++) {              // 2048 elems of A
            int idx = tid + i * 256;
            int m = idx >> 5, k = idx & 31;
            As[k][m] = A[(size_t)(row0 + m) * EE + k0 + k];
        }
        #pragma unroll
        for (int i = 0; i < 8; i++) {              // 2048 elems of W
            int idx = tid + i * 256;
            int k = idx >> 6, n = idx & 63;
            Ws[k][n] = W[(size_t)(k0 + k) * HH + n];
        }
        __syncthreads();

        #pragma unroll
        for (int k = 0; k < 32; k++) {
            float a[4], w[4];
            #pragma unroll
            for (int i = 0; i < 4; i++) a[i] = As[k][ty * 4 + i];
            #pragma unroll
            for (int j = 0; j < 4; j++) w[j] = Ws[k][tx * 4 + j];
            #pragma unroll
            for (int i = 0; i < 4; i++)
                #pragma unroll
                for (int j = 0; j < 4; j++)
                    acc[i][j] += a[i] * w[j];
        }
        __syncthreads();
    }

    #pragma unroll
    for (int i = 0; i < 4; i++) {
        int m = row0 + ty * 4 + i;
        #pragma unroll
        for (int j = 0; j < 4; j++) {
            int n = tx * 4 + j;
            C[(size_t)m * HH + n] = acc[i][j] + bias[n];
        }
    }
}

// ---------------- flash attention ------------------------------------------
// Per block: one (batch, 64-query) tile. Stream over 32 key tiles of 64.
// Online softmax with reference semantics: masked scores = 1e-10 (NOT -inf),
// included in the softmax.
struct AttnSmem {
    float Qs[64][65];   // Qs[m][h]
    float Ks[64][65];   // Ks[h][n]  (K transposed on load)
    float Ps[64][65];   // Ps[m][n]  probabilities (unnormalized)
    float Vs[64][64];   // Vs[k][h]
    float red[16][65];  // red[tx][row] partial max / sum
    float m_s[64];
    float l_s[64];
    float alpha_s[64];
};

__global__ __launch_bounds__(256) void attn_kernel(
    const void* __restrict__ mask, float* __restrict__ Out)
{
    extern __shared__ char smem_raw[];
    AttnSmem& sm = *reinterpret_cast<AttnSmem*>(smem_raw);

    const int b   = blockIdx.y;
    const int q0  = blockIdx.x * 64;
    const int tid = threadIdx.x;
    const int tx  = tid & 15;   // H columns (4 each)
    const int ty  = tid >> 4;   // query rows (4 each)

    const float* Q = g_Q + (size_t)b * SS * HH;
    const float* K = g_K + (size_t)b * SS * HH;
    const float* V = g_V + (size_t)b * SS * HH;
    const int mmode = g_mask_mode;

    // load Q tile [64 rows][64 h]
    #pragma unroll
    for (int i = 0; i < 16; i++) {
        int idx = tid + i * 256;
        int m = idx >> 6, h = idx & 63;
        sm.Qs[m][h] = Q[(size_t)(q0 + m) * HH + h];
    }
    if (tid < 64) { sm.m_s[tid] = -INFINITY; sm.l_s[tid] = 0.f; }

    float acc[4][4] = {};

    for (int kt = 0; kt < 32; kt++) {
        const int k0 = kt * 64;
        __syncthreads();   // (A) prev GEMM2 done reading Ks/Vs/Ps, red readers done

        #pragma unroll
        for (int i = 0; i < 16; i++) {             // K tile, transposed
            int idx = tid + i * 256;
            int n = idx >> 6, h = idx & 63;
            sm.Ks[h][n] = K[(size_t)(k0 + n) * HH + h];
        }
        #pragma unroll
        for (int i = 0; i < 16; i++) {             // V tile
            int idx = tid + i * 256;
            int k = idx >> 6, h = idx & 63;
            sm.Vs[k][h] = V[(size_t)(k0 + k) * HH + h];
        }
        __syncthreads();   // (B)

        // GEMM1: s[m][n] = sum_h Q[m][h] * K[n][h]
        float s[4][4] = {};
        #pragma unroll
        for (int h = 0; h < 64; h++) {
            float a[4], kk[4];
            #pragma unroll
            for (int i = 0; i < 4; i++) a[i]  = sm.Qs[ty * 4 + i][h];
            #pragma unroll
            for (int j = 0; j < 4; j++) kk[j] = sm.Ks[h][tx * 4 + j];
            #pragma unroll
            for (int i = 0; i < 4; i++)
                #pragma unroll
                for (int j = 0; j < 4; j++)
                    s[i][j] += a[i] * kk[j];
        }

        // scale + masked fill (mask==true -> 1e-10, reference semantics)
        #pragma unroll
        for (int i = 0; i < 4; i++) {
            const size_t eoff = ((size_t)b * SS + (q0 + ty * 4 + i)) * SS + k0 + tx * 4;
            if (mmode == 1) {
                unsigned mv = *reinterpret_cast<const unsigned*>(
                    reinterpret_cast<const unsigned char*>(mask) + eoff);
                #pragma unroll
                for (int j = 0; j < 4; j++) {
                    bool mk = ((mv >> (8 * j)) & 0xFFu) != 0u;
                    s[i][j] = mk ? 1e-10f : s[i][j] * 0.125f;
                }
            } else if (mmode == 0) {
                int4 mv = *reinterpret_cast<const int4*>(
                    reinterpret_cast<const int*>(mask) + eoff);
                int mvv[4] = { mv.x, mv.y, mv.z, mv.w };
                #pragma unroll
                for (int j = 0; j < 4; j++)
                    s[i][j] = (mvv[j] != 0) ? 1e-10f : s[i][j] * 0.125f;
            } else {
                float4 mv = *reinterpret_cast<const float4*>(
                    reinterpret_cast<const float*>(mask) + eoff);
                float mvv[4] = { mv.x, mv.y, mv.z, mv.w };
                #pragma unroll
                for (int j = 0; j < 4; j++)
                    s[i][j] = (mvv[j] != 0.f) ? 1e-10f : s[i][j] * 0.125f;
            }
        }

        // per-row partial max
        #pragma unroll
        for (int i = 0; i < 4; i++) {
            float pm = fmaxf(fmaxf(s[i][0], s[i][1]), fmaxf(s[i][2], s[i][3]));
            sm.red[tx][ty * 4 + i] = pm;
        }
        __syncthreads();   // (C)

        if (tid < 64) {
            float mx = sm.red[0][tid];
            #pragma unroll
            for (int t = 1; t < 16; t++) mx = fmaxf(mx, sm.red[t][tid]);
            float m_old = sm.m_s[tid];
            float m_new = fmaxf(m_old, mx);
            sm.m_s[tid]     = m_new;
            sm.alpha_s[tid] = __expf(m_old - m_new);   // 0 on first tile
        }
        __syncthreads();   // (D)

        // p = exp(s - m_new); write Ps; partial row sums; rescale O acc
        #pragma unroll
        for (int i = 0; i < 4; i++) {
            const int r  = ty * 4 + i;
            const float mn = sm.m_s[r];
            float rs = 0.f;
            #pragma unroll
            for (int j = 0; j < 4; j++) {
                float p = __expf(s[i][j] - mn);
                sm.Ps[r][tx * 4 + j] = p;
                rs += p;
            }
            sm.red[tx][r] = rs;
            const float al = sm.alpha_s[r];
            #pragma unroll
            for (int j = 0; j < 4; j++) acc[i][j] *= al;
        }
        __syncthreads();   // (E)

        if (tid < 64) {
            float ssum = 0.f;
            #pragma unroll
            for (int t = 0; t < 16; t++) ssum += sm.red[t][tid];
            sm.l_s[tid] = sm.l_s[tid] * sm.alpha_s[tid] + ssum;
        }

        // GEMM2: acc[m][h] += sum_k Ps[m][k] * Vs[k][h]
        #pragma unroll
        for (int k = 0; k < 64; k++) {
            float pv[4], vv[4];
            #pragma unroll
            for (int i = 0; i < 4; i++) pv[i] = sm.Ps[ty * 4 + i][k];
            #pragma unroll
            for (int j = 0; j < 4; j++) vv[j] = sm.Vs[k][tx * 4 + j];
            #pragma unroll
            for (int i = 0; i < 4; i++)
                #pragma unroll
                for (int j = 0; j < 4; j++)
                    acc[i][j] += pv[i] * vv[j];
        }
    }
    __syncthreads();  // l_s final

    #pragma unroll
    for (int i = 0; i < 4; i++) {
        const int r = ty * 4 + i;
        const float inv = 1.f / sm.l_s[r];
        #pragma unroll
        for (int j = 0; j < 4; j++)
            Out[((size_t)b * SS + (q0 + r)) * HH + tx * 4 + j] = acc[i][j] * inv;
    }
}

// ---------------- launch ----------------------------------------------------
extern "C" void kernel_launch(void* const* d_in, const int* in_sizes, int n_in,
                              void* d_out, int out_size)
{
    const float* iQ = (const float*)d_in[0];
    const float* iK = (const float*)d_in[1];
    const float* iV = (const float*)d_in[2];
    const void*  mask = d_in[3];
    const float* Wq = (const float*)d_in[4];
    const float* bq = (const float*)d_in[5];
    const float* Wk = (const float*)d_in[6];
    const float* bk = (const float*)d_in[7];
    const float* Wv = (const float*)d_in[8];
    const float* bv = (const float*)d_in[9];
    float* out = (float*)d_out;

    // >48KB dynamic smem opt-in (capture-safe: no allocation, no stream sync)
    cudaFuncSetAttribute(attn_kernel, cudaFuncAttributeMaxDynamicSharedMemorySize,
                         (int)sizeof(AttnSmem));

    detect_mask_kernel<<<1, 32>>>((const unsigned int*)mask);

    dim3 pgrid(BSROWS / 64, 3);
    proj_kernel<<<pgrid, 256>>>(iQ, iK, iV, Wq, Wk, Wv, bq, bk, bv);

    dim3 agrid(SS / 64, BB);
    attn_kernel<<<agrid, 256, sizeof(AttnSmem)>>>(mask, out);
}

// round 3
// speedup vs baseline: 1.0029x; 1.0029x over previous
#include <cuda_runtime.h>
#include <cstdint>

// Problem constants
#define BB 8
#define SS 2048
#define EE 1024
#define HH 64
#define BSROWS (BB*SS)   // 16384

// ---------------- scratch (device globals; no allocation allowed) ----------
__device__ float g_Q[BB*SS*HH];
__device__ float g_K[BB*SS*HH];
__device__ float g_V[BB*SS*HH];
__device__ int   g_mask_mode;   // 0 = int32, 1 = uint8/bool, 2 = float32

// ---------------- mask dtype detection -------------------------------------
// jax bool may arrive as 1-byte bool, promoted int32, or float32. Classify by
// inspecting the first 256 32-bit words (mask buffer is >= 33 MB, safe).
__global__ void detect_mask_kernel(const unsigned int* __restrict__ m) {
    if (threadIdx.x == 0 && blockIdx.x == 0) {
        bool all_01 = true;      // int32 with values {0,1}
        bool all_f  = true;      // float32 with values {0.0f,1.0f}
        for (int i = 0; i < 256; i++) {
            unsigned v = m[i];
            if (v > 1u) all_01 = false;
            if (v != 0u && v != 0x3F800000u) all_f = false;
        }
        g_mask_mode = all_01 ? 0 : (all_f ? 2 : 1);
    }
}

// ---------------- fused QKV projection -------------------------------------
// C[M=16384, N=64] = A[M,1024] @ W[1024,64] + bias.  blockIdx.y selects Q/K/V.
// 64x64 output tile per block, K-tiles of 32, 4x4 register microtile / thread.
__global__ __launch_bounds__(256) void proj_kernel(
    const float* __restrict__ A0, const float* __restrict__ A1, const float* __restrict__ A2,
    const float* __restrict__ W0, const float* __restrict__ W1, const float* __restrict__ W2,
    const float* __restrict__ b0, const float* __restrict__ b1, const float* __restrict__ b2)
{
    const float *A, *W, *bias; float* C;
    if (blockIdx.y == 0)      { A = A0; W = W0; bias = b0; C = g_Q; }
    else if (blockIdx.y == 1) { A = A1; W = W1; bias = b1; C = g_K; }
    else                      { A = A2; W = W2; bias = b2; C = g_V; }

    __shared__ float As[32][65];   // A tile transposed: As[k][m]
    __shared__ float Ws[32][64];   // W tile:            Ws[k][n]

    const int tid = threadIdx.x;
    const int tx  = tid & 15;      // 16 col-groups (n)
    const int ty  = tid >> 4;      // 16 row-groups (m)
    const int row0 = blockIdx.x * 64;

    float acc[4][4] = {};

    for (int k0 = 0; k0 < EE; k0 += 32) {
        #pragma unroll
        for (int i = 0; i < 8; i++) {              // 2048 elems of A
            int idx = tid + i * 256;
            int m = idx >> 5, k = idx & 31;
            As[k][m] = A[(size_t)(row0 + m) * EE + k0 + k];
        }
        #pragma unroll
        for (int i = 0; i < 8; i++) {              // 2048 elems of W
            int idx = tid + i * 256;
            int k = idx >> 6, n = idx & 63;
            Ws[k][n] = W[(size_t)(k0 + k) * HH + n];
        }
        __syncthreads();

        #pragma unroll
        for (int k = 0; k < 32; k++) {
            float a[4], w[4];
            #pragma unroll
            for (int i = 0; i < 4; i++) a[i] = As[k][ty * 4 + i];
            #pragma unroll
            for (int j = 0; j < 4; j++) w[j] = Ws[k][tx * 4 + j];
            #pragma unroll
            for (int i = 0; i < 4; i++)
                #pragma unroll
                for (int j = 0; j < 4; j++)
                    acc[i][j] += a[i] * w[j];
        }
        __syncthreads();
    }

    #pragma unroll
    for (int i = 0; i < 4; i++) {
        int m = row0 + ty * 4 + i;
        #pragma unroll
        for (int j = 0; j < 4; j++) {
            int n = tx * 4 + j;
            C[(size_t)m * HH + n] = acc[i][j] + bias[n];
        }
    }
}

// ---------------- flash attention ------------------------------------------
// Per block: one (batch, 64-query) tile. Stream over 32 key tiles of 64.
// Online softmax with reference semantics: masked scores = 1e-10 (NOT -inf),
// included in the softmax.
struct AttnSmem {
    float Qs[64][65];   // Qs[m][h]
    float Ks[64][65];   // Ks[h][n]  (K transposed on load)
    float Ps[64][65];   // Ps[m][n]  probabilities (unnormalized)
    float Vs[64][64];   // Vs[k][h]
    float red[16][65];  // red[tx][row] partial max / sum
    float m_s[64];
    float l_s[64];
    float alpha_s[64];
};

__global__ __launch_bounds__(256) void attn_kernel(
    const void* __restrict__ mask, float* __restrict__ Out)
{
    extern __shared__ char smem_raw[];
    AttnSmem& sm = *reinterpret_cast<AttnSmem*>(smem_raw);

    const int b   = blockIdx.y;
    const int q0  = blockIdx.x * 64;
    const int tid = threadIdx.x;
    const int tx  = tid & 15;   // H columns (4 each)
    const int ty  = tid >> 4;   // query rows (4 each)

    const float* Q = g_Q + (size_t)b * SS * HH;
    const float* K = g_K + (size_t)b * SS * HH;
    const float* V = g_V + (size_t)b * SS * HH;
    const int mmode = g_mask_mode;

    // load Q tile [64 rows][64 h]
    #pragma unroll
    for (int i = 0; i < 16; i++) {
        int idx = tid + i * 256;
        int m = idx >> 6, h = idx & 63;
        sm.Qs[m][h] = Q[(size_t)(q0 + m) * HH + h];
    }
    if (tid < 64) { sm.m_s[tid] = -INFINITY; sm.l_s[tid] = 0.f; }

    float acc[4][4] = {};

    for (int kt = 0; kt < 32; kt++) {
        const int k0 = kt * 64;
        __syncthreads();   // (A) prev GEMM2 done reading Ks/Vs/Ps, red readers done

        #pragma unroll
        for (int i = 0; i < 16; i++) {             // K tile, transposed
            int idx = tid + i * 256;
            int n = idx >> 6, h = idx & 63;
            sm.Ks[h][n] = K[(size_t)(k0 + n) * HH + h];
        }
        #pragma unroll
        for (int i = 0; i < 16; i++) {             // V tile
            int idx = tid + i * 256;
            int k = idx >> 6, h = idx & 63;
            sm.Vs[k][h] = V[(size_t)(k0 + k) * HH + h];
        }
        __syncthreads();   // (B)

        // GEMM1: s[m][n] = sum_h Q[m][h] * K[n][h]
        float s[4][4] = {};
        #pragma unroll
        for (int h = 0; h < 64; h++) {
            float a[4], kk[4];
            #pragma unroll
            for (int i = 0; i < 4; i++) a[i]  = sm.Qs[ty * 4 + i][h];
            #pragma unroll
            for (int j = 0; j < 4; j++) kk[j] = sm.Ks[h][tx * 4 + j];
            #pragma unroll
            for (int i = 0; i < 4; i++)
                #pragma unroll
                for (int j = 0; j < 4; j++)
                    s[i][j] += a[i] * kk[j];
        }

        // scale + masked fill (mask==true -> 1e-10, reference semantics)
        #pragma unroll
        for (int i = 0; i < 4; i++) {
            const size_t eoff = ((size_t)b * SS + (q0 + ty * 4 + i)) * SS + k0 + tx * 4;
            if (mmode == 1) {
                unsigned mv = *reinterpret_cast<const unsigned*>(
                    reinterpret_cast<const unsigned char*>(mask) + eoff);
                #pragma unroll
                for (int j = 0; j < 4; j++) {
                    bool mk = ((mv >> (8 * j)) & 0xFFu) != 0u;
                    s[i][j] = mk ? 1e-10f : s[i][j] * 0.125f;
                }
            } else if (mmode == 0) {
                int4 mv = *reinterpret_cast<const int4*>(
                    reinterpret_cast<const int*>(mask) + eoff);
                int mvv[4] = { mv.x, mv.y, mv.z, mv.w };
                #pragma unroll
                for (int j = 0; j < 4; j++)
                    s[i][j] = (mvv[j] != 0) ? 1e-10f : s[i][j] * 0.125f;
            } else {
                float4 mv = *reinterpret_cast<const float4*>(
                    reinterpret_cast<const float*>(mask) + eoff);
                float mvv[4] = { mv.x, mv.y, mv.z, mv.w };
                #pragma unroll
                for (int j = 0; j < 4; j++)
                    s[i][j] = (mvv[j] != 0.f) ? 1e-10f : s[i][j] * 0.125f;
            }
        }

        // per-row partial max
        #pragma unroll
        for (int i = 0; i < 4; i++) {
            float pm = fmaxf(fmaxf(s[i][0], s[i][1]), fmaxf(s[i][2], s[i][3]));
            sm.red[tx][ty * 4 + i] = pm;
        }
        __syncthreads();   // (C)

        if (tid < 64) {
            float mx = sm.red[0][tid];
            #pragma unroll
            for (int t = 1; t < 16; t++) mx = fmaxf(mx, sm.red[t][tid]);
            float m_old = sm.m_s[tid];
            float m_new = fmaxf(m_old, mx);
            sm.m_s[tid]     = m_new;
            sm.alpha_s[tid] = __expf(m_old - m_new);   // 0 on first tile
        }
        __syncthreads();   // (D)

        // p = exp(s - m_new); write Ps; partial row sums; rescale O acc
        #pragma unroll
        for (int i = 0; i < 4; i++) {
            const int r  = ty * 4 + i;
            const float mn = sm.m_s[r];
            float rs = 0.f;
            #pragma unroll
            for (int j = 0; j < 4; j++) {
                float p = __expf(s[i][j] - mn);
                sm.Ps[r][tx * 4 + j] = p;
                rs += p;
            }
            sm.red[tx][r] = rs;
            const float al = sm.alpha_s[r];
            #pragma unroll
            for (int j = 0; j < 4; j++) acc[i][j] *= al;
        }
        __syncthreads();   // (E)

        if (tid < 64) {
            float ssum = 0.f;
            #pragma unroll
            for (int t = 0; t < 16; t++) ssum += sm.red[t][tid];
            sm.l_s[tid] = sm.l_s[tid] * sm.alpha_s[tid] + ssum;
        }

        // GEMM2: acc[m][h] += sum_k Ps[m][k] * Vs[k][h]
        #pragma unroll
        for (int k = 0; k < 64; k++) {
            float pv[4], vv[4];
            #pragma unroll
            for (int i = 0; i < 4; i++) pv[i] = sm.Ps[ty * 4 + i][k];
            #pragma unroll
            for (int j = 0; j < 4; j++) vv[j] = sm.Vs[k][tx * 4 + j];
            #pragma unroll
            for (int i = 0; i < 4; i++)
                #pragma unroll
                for (int j = 0; j < 4; j++)
                    acc[i][j] += pv[i] * vv[j];
        }
    }
    __syncthreads();  // l_s final

    #pragma unroll
    for (int i = 0; i < 4; i++) {
        const int r = ty * 4 + i;
        const float inv = 1.f / sm.l_s[r];
        #pragma unroll
        for (int j = 0; j < 4; j++)
            Out[((size_t)b * SS + (q0 + r)) * HH + tx * 4 + j] = acc[i][j] * inv;
    }
}

// ---------------- launch ----------------------------------------------------
extern "C" void kernel_launch(void* const* d_in, const int* in_sizes, int n_in,
                              void* d_out, int out_size)
{
    const float* iQ = (const float*)d_in[0];
    const float* iK = (const float*)d_in[1];
    const float* iV = (const float*)d_in[2];
    const void*  mask = d_in[3];
    const float* Wq = (const float*)d_in[4];
    const float* bq = (const float*)d_in[5];
    const float* Wk = (const float*)d_in[6];
    const float* bk = (const float*)d_in[7];
    const float* Wv = (const float*)d_in[8];
    const float* bv = (const float*)d_in[9];
    float* out = (float*)d_out;

    // >48KB dynamic smem opt-in (capture-safe: no allocation, no stream sync)
    cudaFuncSetAttribute(attn_kernel, cudaFuncAttributeMaxDynamicSharedMemorySize,
                         (int)sizeof(AttnSmem));

    detect_mask_kernel<<<1, 32>>>((const unsigned int*)mask);

    dim3 pgrid(BSROWS / 64, 3);
    proj_kernel<<<pgrid, 256>>>(iQ, iK, iV, Wq, Wk, Wv, bq, bk, bv);

    dim3 agrid(SS / 64, BB);
    attn_kernel<<<agrid, 256, sizeof(AttnSmem)>>>(mask, out);
}

// round 5
// speedup vs baseline: 1.6194x; 1.6148x over previous
#include <cuda_runtime.h>
#include <cuda_bf16.h>
#include <cstdint>

#define BB 8
#define SS 2048
#define EE 1024
#define HH 64
#define NROWS (BB*SS)
#define LDT 72          // padded row stride in bf16 elems for 64-col tiles
#define LDTB (LDT*2)    // 144 bytes

// ---------------- device-global scratch (no allocation allowed) -------------
__device__ unsigned short g_Qhi[NROWS*HH];
__device__ unsigned short g_Qlo[NROWS*HH];
__device__ unsigned short g_Khi[NROWS*HH];
__device__ unsigned short g_Klo[NROWS*HH];
__device__ unsigned short g_Vhi[NROWS*HH];
__device__ unsigned short g_Vlo[NROWS*HH];
__device__ unsigned g_mask_bits[(size_t)BB*SS*(SS/32)];
__device__ int g_mask_mode;   // 0=int32, 1=uint8, 2=float32

// ---------------- base-ISA tensor helpers (sm_80+, no 'a' gating) -----------
__device__ __forceinline__ uint32_t smem_u32(const void* p) {
    uint32_t a;
    asm("{ .reg .u64 t; cvta.to.shared.u64 t, %1; cvt.u32.u64 %0, t; }" : "=r"(a) : "l"(p));
    return a;
}
__device__ __forceinline__ void ldsm4(uint32_t* r, uint32_t a) {
    asm volatile("ldmatrix.sync.aligned.m8n8.x4.shared.b16 {%0,%1,%2,%3}, [%4];"
        : "=r"(r[0]), "=r"(r[1]), "=r"(r[2]), "=r"(r[3]) : "r"(a));
}
__device__ __forceinline__ void ldsm4t(uint32_t* r, uint32_t a) {
    asm volatile("ldmatrix.sync.aligned.m8n8.x4.trans.shared.b16 {%0,%1,%2,%3}, [%4];"
        : "=r"(r[0]), "=r"(r[1]), "=r"(r[2]), "=r"(r[3]) : "r"(a));
}
__device__ __forceinline__ void mma16816(float* c, const uint32_t* a, uint32_t b0, uint32_t b1) {
    asm volatile("mma.sync.aligned.m16n8k16.row.col.f32.bf16.bf16.f32 "
        "{%0,%1,%2,%3}, {%4,%5,%6,%7}, {%8,%9}, {%0,%1,%2,%3};"
        : "+f"(c[0]), "+f"(c[1]), "+f"(c[2]), "+f"(c[3])
        : "r"(a[0]), "r"(a[1]), "r"(a[2]), "r"(a[3]), "r"(b0), "r"(b1));
}
// split x0,x1 into packed bf16x2 hi-word and lo-word (2-term Dekker split)
__device__ __forceinline__ void split2(float x0, float x1, uint32_t& hw, uint32_t& lw) {
    __nv_bfloat16 h0 = __float2bfloat16(x0), h1 = __float2bfloat16(x1);
    float r0 = x0 - __bfloat162float(h0);
    float r1 = x1 - __bfloat162float(h1);
    __nv_bfloat16 l0 = __float2bfloat16(r0), l1 = __float2bfloat16(r1);
    hw = (uint32_t)__bfloat16_as_ushort(h0) | ((uint32_t)__bfloat16_as_ushort(h1) << 16);
    lw = (uint32_t)__bfloat16_as_ushort(l0) | ((uint32_t)__bfloat16_as_ushort(l1) << 16);
}

// ---------------- mask detect + bitpack -------------------------------------
__global__ void detect_mask_kernel(const unsigned int* __restrict__ m) {
    const int lane = threadIdx.x;
    bool all_01 = true, all_f = true;
    for (int i = lane; i < 256; i += 32) {
        unsigned v = m[i];
        if (v > 1u) all_01 = false;
        if (v != 0u && v != 0x3F800000u) all_f = false;
    }
    all_01 = __all_sync(0xFFFFFFFFu, all_01);
    all_f  = __all_sync(0xFFFFFFFFu, all_f);
    if (lane == 0) g_mask_mode = all_01 ? 0 : (all_f ? 2 : 1);
}
__global__ __launch_bounds__(256) void pack_mask_kernel(const void* __restrict__ mask) {
    size_t i = (size_t)blockIdx.x * 256 + threadIdx.x;
    bool mv;
    if (g_mask_mode == 1) mv = ((const unsigned char*)mask)[i] != 0;
    else                  mv = ((const unsigned*)mask)[i] != 0u;
    unsigned w = __ballot_sync(0xFFFFFFFFu, mv);
    if ((threadIdx.x & 31) == 0) g_mask_bits[i >> 5] = w;
}

// ---------------- projection: HMMA bf16x3, 128x64 tile per CTA --------------
// smem: A_hi[128][72], A_lo, W_hi[64][72], W_lo  (bf16, padded rows)
#define PJ_AH 0
#define PJ_AL (PJ_AH + 128*LDTB)
#define PJ_WH (PJ_AL + 128*LDTB)
#define PJ_WL (PJ_WH + 64*LDTB)
#define PJ_SMEM (PJ_WL + 64*LDTB)

__global__ __launch_bounds__(256, 1) void proj_kernel(
    const float* __restrict__ A0, const float* __restrict__ A1, const float* __restrict__ A2,
    const float* __restrict__ W0, const float* __restrict__ W1, const float* __restrict__ W2,
    const float* __restrict__ b0, const float* __restrict__ b1, const float* __restrict__ b2)
{
    extern __shared__ char smem[];
    const uint32_t sb = smem_u32(smem);
    const int tid  = threadIdx.x;
    const int warp = tid >> 5, lane = tid & 31;
    const int quad = lane & 3, qrow = lane >> 2;

    const float *A, *W, *bias; unsigned short *Oh, *Ol;
    if (blockIdx.y == 0)      { A = A0; W = W0; bias = b0; Oh = g_Qhi; Ol = g_Qlo; }
    else if (blockIdx.y == 1) { A = A1; W = W1; bias = b1; Oh = g_Khi; Ol = g_Klo; }
    else                      { A = A2; W = W2; bias = b2; Oh = g_Vhi; Ol = g_Vlo; }
    const int row0 = blockIdx.x * 128;

    float acc[8][4] = {};

    for (int kc = 0; kc < 16; kc++) {
        const int k0 = kc * 64;
        __syncthreads();
        // stage A chunk [128 rows x 64 k] fp32 -> bf16 hi/lo
        #pragma unroll
        for (int i = 0; i < 16; i++) {
            int idx = tid + i * 256;
            int r = idx >> 5, pr = idx & 31;
            float2 x = *(const float2*)(A + (size_t)(row0 + r) * EE + k0 + pr * 2);
            uint32_t hw, lw; split2(x.x, x.y, hw, lw);
            *(uint32_t*)(smem + PJ_AH + r * LDTB + pr * 4) = hw;
            *(uint32_t*)(smem + PJ_AL + r * LDTB + pr * 4) = lw;
        }
        // stage W chunk [64 e x 64 h]
        #pragma unroll
        for (int i = 0; i < 8; i++) {
            int idx = tid + i * 256;
            int k = idx >> 5, np = idx & 31;
            float2 x = *(const float2*)(W + (size_t)(k0 + k) * HH + np * 2);
            uint32_t hw, lw; split2(x.x, x.y, hw, lw);
            *(uint32_t*)(smem + PJ_WH + k * LDTB + np * 4) = hw;
            *(uint32_t*)(smem + PJ_WL + k * LDTB + np * 4) = lw;
        }
        __syncthreads();

        #pragma unroll
        for (int ks = 0; ks < 4; ks++) {
            uint32_t ah[4], al[4];
            uint32_t aaddr = sb + PJ_AH +
                (uint32_t)((16 * warp + (lane & 15)) * LDTB + (ks * 16 + (lane >> 4) * 8) * 2);
            ldsm4(ah, aaddr);
            ldsm4(al, aaddr + (PJ_AL - PJ_AH));
            #pragma unroll
            for (int nbp = 0; nbp < 4; nbp++) {
                uint32_t wh[4], wl[4];
                uint32_t waddr = sb + PJ_WH +
                    (uint32_t)((ks * 16 + (lane & 15)) * LDTB + (nbp * 16 + (lane >> 4) * 8) * 2);
                ldsm4t(wh, waddr);
                ldsm4t(wl, waddr + (PJ_WL - PJ_WH));
                mma16816(acc[2*nbp],   ah, wh[0], wh[1]);
                mma16816(acc[2*nbp],   ah, wl[0], wl[1]);
                mma16816(acc[2*nbp],   al, wh[0], wh[1]);
                mma16816(acc[2*nbp+1], ah, wh[2], wh[3]);
                mma16816(acc[2*nbp+1], ah, wl[2], wl[3]);
                mma16816(acc[2*nbp+1], al, wh[2], wh[3]);
            }
        }
    }

    // epilogue: +bias, split to hi/lo, store
    const int r0g = row0 + 16 * warp + qrow;
    const int r1g = r0g + 8;
    #pragma unroll
    for (int nb = 0; nb < 8; nb++) {
        const int c = 8 * nb + 2 * quad;
        const float bv0 = bias[c], bv1 = bias[c + 1];
        uint32_t h00, l00, h10, l10;
        split2(acc[nb][0] + bv0, acc[nb][1] + bv1, h00, l00);
        split2(acc[nb][2] + bv0, acc[nb][3] + bv1, h10, l10);
        *(uint32_t*)(Oh + (size_t)r0g * HH + c) = h00;
        *(uint32_t*)(Ol + (size_t)r0g * HH + c) = l00;
        *(uint32_t*)(Oh + (size_t)r1g * HH + c) = h10;
        *(uint32_t*)(Ol + (size_t)r1g * HH + c) = l10;
    }
}

// ---------------- attention: HMMA flash, 128-query tile per CTA -------------
// smem: Q_hi, Q_lo, K_hi, K_lo, V_hi, V_lo — each [128][72] bf16
#define AT_Q_H 0
#define AT_Q_L (AT_Q_H + 128*LDTB)
#define AT_K_H (AT_Q_L + 128*LDTB)
#define AT_K_L (AT_K_H + 128*LDTB)
#define AT_V_H (AT_K_L + 128*LDTB)
#define AT_V_L (AT_V_H + 128*LDTB)
#define AT_SMEM (AT_V_L + 128*LDTB)

__global__ __launch_bounds__(256, 1) void attn_kernel(float* __restrict__ Out)
{
    extern __shared__ char smem[];
    const uint32_t sb = smem_u32(smem);
    const int tid  = threadIdx.x;
    const int warp = tid >> 5, lane = tid & 31;
    const int quad = lane & 3, qrow = lane >> 2;
    const int b  = blockIdx.y;
    const int q0 = blockIdx.x * 128;

    // ---- stage Q tile, build resident Q fragments ----
    {
        const unsigned short* qh = g_Qhi + ((size_t)b * SS + q0) * HH;
        const unsigned short* ql = g_Qlo + ((size_t)b * SS + q0) * HH;
        #pragma unroll
        for (int i = 0; i < 4; i++) {
            int idx = tid + i * 256;
            int r = idx >> 3, cg = idx & 7;
            *(uint4*)(smem + AT_Q_H + r * LDTB + cg * 16) = *(const uint4*)(qh + (size_t)r * HH + cg * 8);
            *(uint4*)(smem + AT_Q_L + r * LDTB + cg * 16) = *(const uint4*)(ql + (size_t)r * HH + cg * 8);
        }
    }
    __syncthreads();
    uint32_t qfh[4][4], qfl[4][4];
    #pragma unroll
    for (int ks = 0; ks < 4; ks++) {
        uint32_t aaddr = sb + AT_Q_H +
            (uint32_t)((16 * warp + (lane & 15)) * LDTB + (ks * 16 + (lane >> 4) * 8) * 2);
        ldsm4(qfh[ks], aaddr);
        ldsm4(qfl[ks], aaddr + (AT_Q_L - AT_Q_H));
    }

    const int r0 = 16 * warp + qrow;       // local row in tile
    const int r1 = r0 + 8;
    const unsigned* mrow0 = g_mask_bits + ((size_t)b * SS + q0 + r0) * (SS / 32);
    const unsigned* mrow1 = g_mask_bits + ((size_t)b * SS + q0 + r1) * (SS / 32);

    float O[8][4] = {};
    float m0 = -INFINITY, m1 = -INFINITY, l0 = 0.f, l1 = 0.f;

    for (int kt = 0; kt < 16; kt++) {
        __syncthreads();
        {   // stage K/V tiles (pre-split bf16)
            const size_t base = ((size_t)b * SS + kt * 128) * HH;
            const unsigned short* kh = g_Khi + base;
            const unsigned short* kl = g_Klo + base;
            const unsigned short* vh = g_Vhi + base;
            const unsigned short* vl = g_Vlo + base;
            #pragma unroll
            for (int i = 0; i < 4; i++) {
                int idx = tid + i * 256;
                int r = idx >> 3, cg = idx & 7;
                size_t s = (size_t)r * HH + cg * 8;
                int d = r * LDTB + cg * 16;
                *(uint4*)(smem + AT_K_H + d) = *(const uint4*)(kh + s);
                *(uint4*)(smem + AT_K_L + d) = *(const uint4*)(kl + s);
                *(uint4*)(smem + AT_V_H + d) = *(const uint4*)(vh + s);
                *(uint4*)(smem + AT_V_L + d) = *(const uint4*)(vl + s);
            }
        }
        __syncthreads();

        // ---- S = Q @ K^T : m16 x n128 x k64 per warp, bf16x3 ----
        float c[16][4] = {};
        #pragma unroll
        for (int ks = 0; ks < 4; ks++) {
            #pragma unroll
            for (int nbp = 0; nbp < 8; nbp++) {
                uint32_t kh[4], kl[4];
                uint32_t kaddr = sb + AT_K_H +
                    (uint32_t)((nbp * 16 + (lane & 15)) * LDTB + (ks * 16 + (lane >> 4) * 8) * 2);
                ldsm4(kh, kaddr);
                ldsm4(kl, kaddr + (AT_K_L - AT_K_H));
                mma16816(c[2*nbp],   qfh[ks], kh[0], kh[2]);
                mma16816(c[2*nbp],   qfh[ks], kl[0], kl[2]);
                mma16816(c[2*nbp],   qfl[ks], kh[0], kh[2]);
                mma16816(c[2*nbp+1], qfh[ks], kh[1], kh[3]);
                mma16816(c[2*nbp+1], qfh[ks], kl[1], kl[3]);
                mma16816(c[2*nbp+1], qfl[ks], kh[1], kh[3]);
            }
        }

        // ---- mask + scale, row max (pass 1) ----
        uint4 mq0 = *(const uint4*)(mrow0 + kt * 4);
        uint4 mq1 = *(const uint4*)(mrow1 + kt * 4);
        const unsigned w0a[4] = { mq0.x, mq0.y, mq0.z, mq0.w };
        const unsigned w1a[4] = { mq1.x, mq1.y, mq1.z, mq1.w };
        float lmax0 = -INFINITY, lmax1 = -INFINITY;
        #pragma unroll
        for (int nb = 0; nb < 16; nb++) {
            const unsigned wm0 = w0a[nb >> 2], wm1 = w1a[nb >> 2];
            #pragma unroll
            for (int jj = 0; jj < 2; jj++) {
                const int col = 8 * nb + 2 * quad + jj;
                const int sh = col & 31;
                float s0 = ((wm0 >> sh) & 1u) ? 1e-10f : c[nb][jj]     * 0.125f;
                float s1 = ((wm1 >> sh) & 1u) ? 1e-10f : c[nb][2 + jj] * 0.125f;
                c[nb][jj]     = s0;
                c[nb][2 + jj] = s1;
                lmax0 = fmaxf(lmax0, s0);
                lmax1 = fmaxf(lmax1, s1);
            }
        }
        lmax0 = fmaxf(lmax0, __shfl_xor_sync(0xFFFFFFFFu, lmax0, 1));
        lmax0 = fmaxf(lmax0, __shfl_xor_sync(0xFFFFFFFFu, lmax0, 2));
        lmax1 = fmaxf(lmax1, __shfl_xor_sync(0xFFFFFFFFu, lmax1, 1));
        lmax1 = fmaxf(lmax1, __shfl_xor_sync(0xFFFFFFFFu, lmax1, 2));
        const float mn0 = fmaxf(m0, lmax0), mn1 = fmaxf(m1, lmax1);
        const float al0 = __expf(m0 - mn0), al1 = __expf(m1 - mn1);
        m0 = mn0; m1 = mn1;

        // ---- exp (pass 2), row sums ----
        float ls0 = 0.f, ls1 = 0.f;
        #pragma unroll
        for (int nb = 0; nb < 16; nb++) {
            float p0 = __expf(c[nb][0] - mn0);
            float p1 = __expf(c[nb][1] - mn0);
            float p2 = __expf(c[nb][2] - mn1);
            float p3 = __expf(c[nb][3] - mn1);
            ls0 += p0 + p1; ls1 += p2 + p3;
            c[nb][0] = p0; c[nb][1] = p1; c[nb][2] = p2; c[nb][3] = p3;
        }
        ls0 += __shfl_xor_sync(0xFFFFFFFFu, ls0, 1);
        ls0 += __shfl_xor_sync(0xFFFFFFFFu, ls0, 2);
        ls1 += __shfl_xor_sync(0xFFFFFFFFu, ls1, 1);
        ls1 += __shfl_xor_sync(0xFFFFFFFFu, ls1, 2);
        l0 = l0 * al0 + ls0;
        l1 = l1 * al1 + ls1;

        // ---- rescale O, then O += P @ V (k=128, bf16x3, P from registers) ----
        #pragma unroll
        for (int nb = 0; nb < 8; nb++) {
            O[nb][0] *= al0; O[nb][1] *= al0;
            O[nb][2] *= al1; O[nb][3] *= al1;
        }
        #pragma unroll
        for (int ks = 0; ks < 8; ks++) {
            uint32_t pah[4], pal[4];
            split2(c[2*ks][0],   c[2*ks][1],   pah[0], pal[0]);
            split2(c[2*ks][2],   c[2*ks][3],   pah[1], pal[1]);
            split2(c[2*ks+1][0], c[2*ks+1][1], pah[2], pal[2]);
            split2(c[2*ks+1][2], c[2*ks+1][3], pah[3], pal[3]);
            #pragma unroll
            for (int nbp = 0; nbp < 4; nbp++) {
                uint32_t vh[4], vl[4];
                uint32_t vaddr = sb + AT_V_H +
                    (uint32_t)((ks * 16 + (lane & 15)) * LDTB + (nbp * 16 + (lane >> 4) * 8) * 2);
                ldsm4t(vh, vaddr);
                ldsm4t(vl, vaddr + (AT_V_L - AT_V_H));
                mma16816(O[2*nbp],   pah, vh[0], vh[1]);
                mma16816(O[2*nbp],   pah, vl[0], vl[1]);
                mma16816(O[2*nbp],   pal, vh[0], vh[1]);
                mma16816(O[2*nbp+1], pah, vh[2], vh[3]);
                mma16816(O[2*nbp+1], pah, vl[2], vl[3]);
                mma16816(O[2*nbp+1], pal, vh[2], vh[3]);
            }
        }
    }

    // ---- normalize + write ----
    const float inv0 = 1.f / l0, inv1 = 1.f / l1;
    float* out0 = Out + ((size_t)b * SS + q0 + r0) * HH;
    float* out1 = Out + ((size_t)b * SS + q0 + r1) * HH;
    #pragma unroll
    for (int nb = 0; nb < 8; nb++) {
        const int col = 8 * nb + 2 * quad;
        *(float2*)(out0 + col) = make_float2(O[nb][0] * inv0, O[nb][1] * inv0);
        *(float2*)(out1 + col) = make_float2(O[nb][2] * inv1, O[nb][3] * inv1);
    }
}

// ---------------- launch ------------------------------------------------------
extern "C" void kernel_launch(void* const* d_in, const int* in_sizes, int n_in,
                              void* d_out, int out_size)
{
    const float* iQ = (const float*)d_in[0];
    const float* iK = (const float*)d_in[1];
    const float* iV = (const float*)d_in[2];
    const void*  mask = d_in[3];
    const float* Wq = (const float*)d_in[4];
    const float* bq = (const float*)d_in[5];
    const float* Wk = (const float*)d_in[6];
    const float* bk = (const float*)d_in[7];
    const float* Wv = (const float*)d_in[8];
    const float* bv = (const float*)d_in[9];
    float* out = (float*)d_out;

    cudaFuncSetAttribute(proj_kernel, cudaFuncAttributeMaxDynamicSharedMemorySize, PJ_SMEM);
    cudaFuncSetAttribute(attn_kernel, cudaFuncAttributeMaxDynamicSharedMemorySize, AT_SMEM);

    detect_mask_kernel<<<1, 32>>>((const unsigned int*)mask);
    pack_mask_kernel<<<(int)(((size_t)BB * SS * SS) / 256), 256>>>(mask);

    dim3 pgrid(NROWS / 128, 3);
    proj_kernel<<<pgrid, 256, PJ_SMEM>>>(iQ, iK, iV, Wq, Wk, Wv, bq, bk, bv);

    dim3 agrid(SS / 128, BB);
    attn_kernel<<<agrid, 256, AT_SMEM>>>(out);
}